// round 1
// baseline (speedup 1.0000x reference)
#include <cuda_runtime.h>
#include <cuda_bf16.h>

#define N_ATOMS 512

struct f3 { float x, y, z; };

__device__ __forceinline__ f3 sub(const f3 a, const f3 b) {
    return { a.x - b.x, a.y - b.y, a.z - b.z };
}
__device__ __forceinline__ f3 cross(const f3 a, const f3 b) {
    return { a.y * b.z - a.z * b.y,
             a.z * b.x - a.x * b.z,
             a.x * b.y - a.y * b.x };
}
__device__ __forceinline__ float dot(const f3 a, const f3 b) {
    return fmaf(a.x, b.x, fmaf(a.y, b.y, a.z * b.z));
}
__device__ __forceinline__ f3 ld3(const float* __restrict__ p) {
    return { __ldg(p), __ldg(p + 1), __ldg(p + 2) };
}
__device__ __forceinline__ float asin_clamped(float x) {
    x = fminf(fmaxf(x, -1.0f), 1.0f);
    return asinf(x);
}

__global__ void writhe_kernel(const float* __restrict__ xyz,
                              const int4* __restrict__ segs,
                              float* __restrict__ out,
                              int n_seg, int n_frames) {
    int s = blockIdx.x * blockDim.x + threadIdx.x;
    if (s >= n_seg) return;

    const int4 sg = segs[s];
    const int i1o = sg.x * 3;
    const int i2o = sg.y * 3;
    const int i3o = sg.z * 3;
    const int i4o = sg.w * 3;

    const float inv2pi = 0.15915494309189535f;

    #pragma unroll 2
    for (int f = 0; f < n_frames; ++f) {
        const float* base = xyz + (size_t)f * (N_ATOMS * 3);

        f3 p1 = ld3(base + i1o);
        f3 p2 = ld3(base + i2o);
        f3 p3 = ld3(base + i3o);
        f3 p4 = ld3(base + i4o);

        f3 r12 = sub(p2, p1);
        f3 r13 = sub(p3, p1);
        f3 r14 = sub(p4, p1);
        f3 r23 = sub(p3, p2);
        f3 r24 = sub(p4, p2);
        f3 r34 = sub(p4, p3);

        f3 c1 = cross(r13, r14);
        f3 c2 = cross(r14, r24);
        f3 c3 = cross(r24, r23);
        f3 c4 = cross(r23, r13);

        float inv1 = rsqrtf(dot(c1, c1));
        float inv2 = rsqrtf(dot(c2, c2));
        float inv3 = rsqrtf(dot(c3, c3));
        float inv4 = rsqrtf(dot(c4, c4));

        float theta = asin_clamped(dot(c1, c2) * inv1 * inv2)
                    + asin_clamped(dot(c2, c3) * inv2 * inv3)
                    + asin_clamped(dot(c3, c4) * inv3 * inv4)
                    + asin_clamped(dot(c4, c1) * inv4 * inv1);

        float sv = dot(cross(r34, r12), r13);
        float sign = (sv > 0.0f) ? 1.0f : ((sv < 0.0f) ? -1.0f : 0.0f);

        out[(size_t)f * n_seg + s] = theta * sign * inv2pi;
    }
}

extern "C" void kernel_launch(void* const* d_in, const int* in_sizes, int n_in,
                              void* d_out, int out_size) {
    const float* xyz = (const float*)d_in[0];
    const int4* segs = (const int4*)d_in[1];
    float* out = (float*)d_out;

    int n_seg = in_sizes[1] / 4;
    int n_frames = in_sizes[0] / (N_ATOMS * 3);

    int threads = 256;
    int blocks = (n_seg + threads - 1) / threads;
    writhe_kernel<<<blocks, threads>>>(xyz, segs, out, n_seg, n_frames);
}

// round 2
// speedup vs baseline: 1.3630x; 1.3630x over previous
#include <cuda_runtime.h>
#include <cuda_bf16.h>

#define N_ATOMS 512
#define FRAME_CHUNKS 8   // grid.y; frames per thread = n_frames / FRAME_CHUNKS

struct f3 { float x, y, z; };

__device__ __forceinline__ f3 sub3(const f3 a, const f3 b) {
    return { a.x - b.x, a.y - b.y, a.z - b.z };
}
__device__ __forceinline__ f3 cross3(const f3 a, const f3 b) {
    return { fmaf(a.y, b.z, -a.z * b.y),
             fmaf(a.z, b.x, -a.x * b.z),
             fmaf(a.x, b.y, -a.y * b.x) };
}
__device__ __forceinline__ float dot3(const f3 a, const f3 b) {
    return fmaf(a.x, b.x, fmaf(a.y, b.y, a.z * b.z));
}
__device__ __forceinline__ f3 ld3(const float* __restrict__ p) {
    return { __ldg(p), __ldg(p + 1), __ldg(p + 2) };
}
__device__ __forceinline__ float sqrt_approx(float z) {
    float r;
    asm("sqrt.approx.f32 %0, %1;" : "=f"(r) : "f"(z));
    return r;
}

// Branch-free asin with clamp to [-1,1]. Cephes-style, ~1e-7 abs error.
__device__ __forceinline__ float asin_clamped(float x) {
    float a  = fminf(fabsf(x), 1.0f);
    bool hi  = a > 0.5f;
    float z  = hi ? fmaf(-0.5f, a, 0.5f) : a * a;   // (1-a)/2  or  a^2
    float sq = sqrt_approx(z);                      // MUFU.SQRT (exact at 0)
    float s  = hi ? sq : a;
    float p  = 4.2163199048e-2f;
    p = fmaf(p, z, 2.4181311049e-2f);
    p = fmaf(p, z, 4.5470025998e-2f);
    p = fmaf(p, z, 7.4953002686e-2f);
    p = fmaf(p, z, 1.6666752422e-1f);
    float r  = fmaf(p * z, s, s);                   // asin(s) for s in [0, ~0.71]
    float res = hi ? fmaf(-2.0f, r, 1.5707963705062866f) : r;
    return copysignf(res, x);
}

__global__ void writhe_kernel(const float* __restrict__ xyz,
                              const int4* __restrict__ segs,
                              float* __restrict__ out,
                              int n_seg, int frames_per_chunk) {
    int s = blockIdx.x * blockDim.x + threadIdx.x;
    if (s >= n_seg) return;

    const int4 sg = segs[s];
    const int i1o = sg.x * 3;
    const int i2o = sg.y * 3;
    const int i3o = sg.z * 3;
    const int i4o = sg.w * 3;

    const int f0 = blockIdx.y * frames_per_chunk;
    const float* base = xyz + (size_t)f0 * (N_ATOMS * 3);
    float* op = out + (size_t)f0 * n_seg + s;

    const float inv2pi = 0.15915494309189535f;

    for (int f = 0; f < frames_per_chunk; ++f) {
        f3 p1 = ld3(base + i1o);
        f3 p2 = ld3(base + i2o);
        f3 p3 = ld3(base + i3o);
        f3 p4 = ld3(base + i4o);
        base += N_ATOMS * 3;

        // Only three base vectors needed.
        f3 r12 = sub3(p2, p1);
        f3 r13 = sub3(p3, p1);
        f3 r14 = sub3(p4, p1);

        // c1 = r13 x r14
        // c2 = r14 x r24 = r12 x r14
        // c4 = r23 x r13 = -(r12 x r13)
        // c3 = r24 x r23 = c2 + c4 - c1
        f3 c1 = cross3(r13, r14);
        f3 c2 = cross3(r12, r14);
        f3 c4m = cross3(r12, r13);          // = -c4
        f3 c3 = { c2.x - c4m.x - c1.x,
                  c2.y - c4m.y - c1.y,
                  c2.z - c4m.z - c1.z };

        float inv1 = rsqrtf(dot3(c1, c1));
        float inv2 = rsqrtf(dot3(c2, c2));
        float inv3 = rsqrtf(dot3(c3, c3));
        float inv4 = rsqrtf(dot3(c4m, c4m)); // |c4m| == |c4|

        // dots with c4 flip sign relative to c4m
        float d12 =  dot3(c1, c2)  * inv1 * inv2;
        float d23 = -dot3(c2, c3)  * inv2 * inv3;   // asin(dot(n2,n3)) with n3 = c3/|c3|... see below
        float d34 = -dot3(c3, c4m) * inv3 * inv4;   // dot(c3, c4) = -dot(c3, c4m)
        float d41 = -dot3(c4m, c1) * inv4 * inv1;   // dot(c4, c1) = -dot(c4m, c1)

        // NOTE: d23 uses +dot(c2,c3): fix sign (c3 is the true c3, no flip needed)
        d23 = -d23; // revert: dot(n2,n3) = dot(c2,c3)*inv2*inv3

        float theta = asin_clamped(d12)
                    + asin_clamped(d23)
                    + asin_clamped(d34)
                    + asin_clamped(d41);

        // sign(dot(cross(r34,r12), r13)) == sign(-dot(c2, r13))
        float sv = -dot3(c2, r13);
        float sign = (sv > 0.0f) ? 1.0f : ((sv < 0.0f) ? -1.0f : 0.0f);

        *op = theta * sign * inv2pi;
        op += n_seg;
    }
}

extern "C" void kernel_launch(void* const* d_in, const int* in_sizes, int n_in,
                              void* d_out, int out_size) {
    const float* xyz = (const float*)d_in[0];
    const int4* segs = (const int4*)d_in[1];
    float* out = (float*)d_out;

    int n_seg = in_sizes[1] / 4;
    int n_frames = in_sizes[0] / (N_ATOMS * 3);

    int chunks = FRAME_CHUNKS;
    if (n_frames % chunks != 0) chunks = 1;   // safety for odd frame counts
    int frames_per_chunk = n_frames / chunks;

    int threads = 256;
    dim3 grid((n_seg + threads - 1) / threads, chunks);
    writhe_kernel<<<grid, threads>>>(xyz, segs, out, n_seg, frames_per_chunk);
}

// round 3
// speedup vs baseline: 1.5702x; 1.1520x over previous
#include <cuda_runtime.h>
#include <cuda_bf16.h>

#define N_ATOMS 512
#define FRAME_CHUNKS 8

typedef unsigned long long ull;

// ---------- packed f32x2 primitives ----------
__device__ __forceinline__ ull pk2(float lo, float hi) {
    ull r;
    asm("mov.b64 %0, {%1, %2};" : "=l"(r) : "f"(lo), "f"(hi));
    return r;
}
#define UNPK(lo, hi, v) asm("mov.b64 {%0, %1}, %2;" : "=f"(lo), "=f"(hi) : "l"(v))

__device__ __forceinline__ ull pmul(ull a, ull b) {
    ull d; asm("mul.rn.f32x2 %0, %1, %2;" : "=l"(d) : "l"(a), "l"(b)); return d;
}
__device__ __forceinline__ ull padd(ull a, ull b) {
    ull d; asm("add.rn.f32x2 %0, %1, %2;" : "=l"(d) : "l"(a), "l"(b)); return d;
}
__device__ __forceinline__ ull pfma(ull a, ull b, ull c) {
    ull d; asm("fma.rn.f32x2 %0, %1, %2, %3;" : "=l"(d) : "l"(a), "l"(b), "l"(c)); return d;
}
// a - b = fma(b, -1, a)
__device__ __forceinline__ ull psub(ull a, ull b, ull neg1) { return pfma(b, neg1, a); }
__device__ __forceinline__ ull pneg(ull a, ull neg1) { return pmul(a, neg1); }

// dot of packed 3-vectors
__device__ __forceinline__ ull pdot(ull ax, ull ay, ull az, ull bx, ull by, ull bz) {
    return pfma(ax, bx, pfma(ay, by, pmul(az, bz)));
}

__device__ __forceinline__ float sqrt_approx(float z) {
    float r; asm("sqrt.approx.f32 %0, %1;" : "=f"(r) : "f"(z)); return r;
}

// packed-hybrid asin (clamped to [-1,1]); poly runs packed, selects per-lane
__device__ __forceinline__ ull pasin(ull x) {
    float xa, xb; UNPK(xa, xb, x);
    float aa = fminf(fabsf(xa), 1.0f);
    float ab = fminf(fabsf(xb), 1.0f);
    ull pa = pk2(aa, ab);
    ull zl = pmul(pa, pa);
    float zla, zlb; UNPK(zla, zlb, zl);
    float zha = fmaf(-0.5f, aa, 0.5f);
    float zhb = fmaf(-0.5f, ab, 0.5f);
    bool ha = aa > 0.5f;
    bool hb = ab > 0.5f;
    float za = ha ? zha : zla;
    float zb = hb ? zhb : zlb;
    // sqrt(a^2) == a, so unconditional sqrt gives s in both branches
    float sa = sqrt_approx(za);
    float sb = sqrt_approx(zb);
    ull zp = pk2(za, zb);
    ull sp = pk2(sa, sb);
    ull q = pk2(4.2163199048e-2f, 4.2163199048e-2f);
    q = pfma(q, zp, pk2(2.4181311049e-2f, 2.4181311049e-2f));
    q = pfma(q, zp, pk2(4.5470025998e-2f, 4.5470025998e-2f));
    q = pfma(q, zp, pk2(7.4953002686e-2f, 7.4953002686e-2f));
    q = pfma(q, zp, pk2(1.6666752422e-1f, 1.6666752422e-1f));
    ull t = pmul(q, zp);
    ull r = pfma(t, sp, sp);               // s + s*z*poly
    float ra, rb; UNPK(ra, rb, r);
    float fa = ha ? fmaf(-2.0f, ra, 1.5707963705062866f) : ra;
    float fb = hb ? fmaf(-2.0f, rb, 1.5707963705062866f) : rb;
    fa = copysignf(fa, xa);
    fb = copysignf(fb, xb);
    return pk2(fa, fb);
}

// Compute writhe for one segment, two frames (bases bA, bB). Results in wa, wb.
__device__ __forceinline__ void writhe_pair(
    const float* __restrict__ bA, const float* __restrict__ bB,
    int o1, int o2, int o3, int o4, float& wa, float& wb)
{
    const ull NEG1 = pk2(-1.0f, -1.0f);

    ull P1x = pk2(__ldg(bA + o1),     __ldg(bB + o1));
    ull P1y = pk2(__ldg(bA + o1 + 1), __ldg(bB + o1 + 1));
    ull P1z = pk2(__ldg(bA + o1 + 2), __ldg(bB + o1 + 2));
    ull P2x = pk2(__ldg(bA + o2),     __ldg(bB + o2));
    ull P2y = pk2(__ldg(bA + o2 + 1), __ldg(bB + o2 + 1));
    ull P2z = pk2(__ldg(bA + o2 + 2), __ldg(bB + o2 + 2));
    ull P3x = pk2(__ldg(bA + o3),     __ldg(bB + o3));
    ull P3y = pk2(__ldg(bA + o3 + 1), __ldg(bB + o3 + 1));
    ull P3z = pk2(__ldg(bA + o3 + 2), __ldg(bB + o3 + 2));
    ull P4x = pk2(__ldg(bA + o4),     __ldg(bB + o4));
    ull P4y = pk2(__ldg(bA + o4 + 1), __ldg(bB + o4 + 1));
    ull P4z = pk2(__ldg(bA + o4 + 2), __ldg(bB + o4 + 2));

    // base vectors
    ull r12x = psub(P2x, P1x, NEG1), r12y = psub(P2y, P1y, NEG1), r12z = psub(P2z, P1z, NEG1);
    ull r13x = psub(P3x, P1x, NEG1), r13y = psub(P3y, P1y, NEG1), r13z = psub(P3z, P1z, NEG1);
    ull r14x = psub(P4x, P1x, NEG1), r14y = psub(P4y, P1y, NEG1), r14z = psub(P4z, P1z, NEG1);

    // negated copies for cross products
    ull n12x = pneg(r12x, NEG1), n12y = pneg(r12y, NEG1), n12z = pneg(r12z, NEG1);
    ull n13x = pneg(r13x, NEG1), n13y = pneg(r13y, NEG1), n13z = pneg(r13z, NEG1);

    // c1 = r13 x r14
    ull c1x = pfma(n13z, r14y, pmul(r13y, r14z));
    ull c1y = pfma(n13x, r14z, pmul(r13z, r14x));
    ull c1z = pfma(n13y, r14x, pmul(r13x, r14y));
    // c2 = r12 x r14
    ull c2x = pfma(n12z, r14y, pmul(r12y, r14z));
    ull c2y = pfma(n12x, r14z, pmul(r12z, r14x));
    ull c2z = pfma(n12y, r14x, pmul(r12x, r14y));
    // c4m = r12 x r13  ( = -c4 )
    ull c4x = pfma(n12z, r13y, pmul(r12y, r13z));
    ull c4y = pfma(n12x, r13z, pmul(r12z, r13x));
    ull c4z = pfma(n12y, r13x, pmul(r12x, r13y));
    // c3 = c2 - c4m - c1
    ull c3x = psub(psub(c2x, c4x, NEG1), c1x, NEG1);
    ull c3y = psub(psub(c2y, c4y, NEG1), c1y, NEG1);
    ull c3z = psub(psub(c2z, c4z, NEG1), c1z, NEG1);

    // squared norms
    ull g1 = pdot(c1x, c1y, c1z, c1x, c1y, c1z);
    ull g2 = pdot(c2x, c2y, c2z, c2x, c2y, c2z);
    ull g3 = pdot(c3x, c3y, c3z, c3x, c3y, c3z);
    ull g4 = pdot(c4x, c4y, c4z, c4x, c4y, c4z);

    // adjacent dots (unsigned; c4 sign handled by subtracting asin terms)
    ull h12 = pdot(c1x, c1y, c1z, c2x, c2y, c2z);
    ull h23 = pdot(c2x, c2y, c2z, c3x, c3y, c3z);
    ull h34 = pdot(c3x, c3y, c3z, c4x, c4y, c4z);
    ull h41 = pdot(c4x, c4y, c4z, c1x, c1y, c1z);

    // sign source: sv_ref = -dot(c2, r13)
    ull psv = pdot(c2x, c2y, c2z, r13x, r13y, r13z);

    // inverse norms per-lane (MUFU)
    float g1a, g1b, g2a, g2b, g3a, g3b, g4a, g4b;
    UNPK(g1a, g1b, g1); UNPK(g2a, g2b, g2); UNPK(g3a, g3b, g3); UNPK(g4a, g4b, g4);
    ull I1 = pk2(rsqrtf(g1a), rsqrtf(g1b));
    ull I2 = pk2(rsqrtf(g2a), rsqrtf(g2b));
    ull I3 = pk2(rsqrtf(g3a), rsqrtf(g3b));
    ull I4 = pk2(rsqrtf(g4a), rsqrtf(g4b));

    ull d12 = pmul(pmul(h12, I1), I2);
    ull d23 = pmul(pmul(h23, I2), I3);
    ull d34 = pmul(pmul(h34, I3), I4);   // = -dot(n3,n4)
    ull d41 = pmul(pmul(h41, I4), I1);   // = -dot(n4,n1)

    // theta = asin(d12) + asin(d23) - asin(d34) - asin(d41)
    ull theta = psub(psub(padd(pasin(d12), pasin(d23)), pasin(d34), NEG1),
                     pasin(d41), NEG1);

    float ta, tb, sva, svb;
    UNPK(ta, tb, theta);
    UNPK(sva, svb, psv);

    const float INV2PI = 0.15915494309189535f;
    // sign(-sv): +1 if sv<0, -1 if sv>0, 0 if sv==0; fold inv2pi in
    float ka = (sva < 0.0f) ? INV2PI : ((sva > 0.0f) ? -INV2PI : 0.0f);
    float kb = (svb < 0.0f) ? INV2PI : ((svb > 0.0f) ? -INV2PI : 0.0f);
    wa = ta * ka;
    wb = tb * kb;
}

__global__ void writhe_kernel(const float* __restrict__ xyz,
                              const int4* __restrict__ segs,
                              float* __restrict__ out,
                              int n_seg, int frames_per_chunk) {
    int s = blockIdx.x * blockDim.x + threadIdx.x;
    if (s >= n_seg) return;

    const int4 sg = segs[s];
    const int o1 = sg.x * 3;
    const int o2 = sg.y * 3;
    const int o3 = sg.z * 3;
    const int o4 = sg.w * 3;

    const int f0 = blockIdx.y * frames_per_chunk;
    const float* bA = xyz + (size_t)f0 * (N_ATOMS * 3);
    float* op = out + (size_t)f0 * n_seg + s;

    const int npairs = frames_per_chunk >> 1;
    for (int p = 0; p < npairs; ++p) {
        const float* bB = bA + N_ATOMS * 3;
        float wa, wb;
        writhe_pair(bA, bB, o1, o2, o3, o4, wa, wb);
        op[0] = wa;
        op[n_seg] = wb;
        op += 2 * (size_t)n_seg;
        bA += 2 * (N_ATOMS * 3);
    }
    if (frames_per_chunk & 1) {
        float wa, wb;
        writhe_pair(bA, bA, o1, o2, o3, o4, wa, wb);
        op[0] = wa;
    }
}

extern "C" void kernel_launch(void* const* d_in, const int* in_sizes, int n_in,
                              void* d_out, int out_size) {
    const float* xyz = (const float*)d_in[0];
    const int4* segs = (const int4*)d_in[1];
    float* out = (float*)d_out;

    int n_seg = in_sizes[1] / 4;
    int n_frames = in_sizes[0] / (N_ATOMS * 3);

    int chunks = FRAME_CHUNKS;
    if (n_frames % chunks != 0) chunks = 1;
    int frames_per_chunk = n_frames / chunks;

    int threads = 256;
    dim3 grid((n_seg + threads - 1) / threads, chunks);
    writhe_kernel<<<grid, threads>>>(xyz, segs, out, n_seg, frames_per_chunk);
}

// round 4
// speedup vs baseline: 1.5783x; 1.0052x over previous
#include <cuda_runtime.h>
#include <cuda_bf16.h>

#define N_ATOMS 512
#define FRAME_STRIDE (N_ATOMS * 3)   // floats per frame
#define FRAME_CHUNKS 8

typedef unsigned long long ull;

// ---------- packed f32x2 primitives ----------
__device__ __forceinline__ ull pk2(float lo, float hi) {
    ull r;
    asm("mov.b64 %0, {%1, %2};" : "=l"(r) : "f"(lo), "f"(hi));
    return r;
}
#define UNPK(lo, hi, v) asm("mov.b64 {%0, %1}, %2;" : "=f"(lo), "=f"(hi) : "l"(v))

__device__ __forceinline__ ull pmul(ull a, ull b) {
    ull d; asm("mul.rn.f32x2 %0, %1, %2;" : "=l"(d) : "l"(a), "l"(b)); return d;
}
__device__ __forceinline__ ull padd(ull a, ull b) {
    ull d; asm("add.rn.f32x2 %0, %1, %2;" : "=l"(d) : "l"(a), "l"(b)); return d;
}
__device__ __forceinline__ ull pfma(ull a, ull b, ull c) {
    ull d; asm("fma.rn.f32x2 %0, %1, %2, %3;" : "=l"(d) : "l"(a), "l"(b), "l"(c)); return d;
}
__device__ __forceinline__ ull psub(ull a, ull b, ull neg1) { return pfma(b, neg1, a); }
__device__ __forceinline__ ull pneg(ull a, ull neg1) { return pmul(a, neg1); }

__device__ __forceinline__ ull pdot(ull ax, ull ay, ull az, ull bx, ull by, ull bz) {
    return pfma(ax, bx, pfma(ay, by, pmul(az, bz)));
}

__device__ __forceinline__ float sqrt_approx(float z) {
    float r; asm("sqrt.approx.f32 %0, %1;" : "=f"(r) : "f"(z)); return r;
}

// Uniform branch-free asin (clamped):
//   a = min(|x|,1); z = (1-a)/2; s = sqrt(z)
//   asin(a) = pi/2 - 2*(s + s*z*P(z))      (P valid since z in [0,0.5])
//   asin(x) = copysign(asin(a), x)
__device__ __forceinline__ ull pasin_u(ull x) {
    const ull NEGHALF = pk2(-0.5f, -0.5f);
    const ull HALF    = pk2(0.5f, 0.5f);
    const ull NEG2    = pk2(-2.0f, -2.0f);
    const ull PIHALF  = pk2(1.5707963705062866f, 1.5707963705062866f);
    const ull C5 = pk2(4.2163199048e-2f, 4.2163199048e-2f);
    const ull C4 = pk2(2.4181311049e-2f, 2.4181311049e-2f);
    const ull C3 = pk2(4.5470025998e-2f, 4.5470025998e-2f);
    const ull C2 = pk2(7.4953002686e-2f, 7.4953002686e-2f);
    const ull C1 = pk2(1.6666752422e-1f, 1.6666752422e-1f);

    float xa, xb; UNPK(xa, xb, x);
    float aa = fminf(fabsf(xa), 1.0f);
    float ab = fminf(fabsf(xb), 1.0f);
    ull ap = pk2(aa, ab);
    ull z  = pfma(ap, NEGHALF, HALF);            // (1-a)/2  >= 0
    float za, zb; UNPK(za, zb, z);
    ull s  = pk2(sqrt_approx(za), sqrt_approx(zb));
    ull q  = pfma(C5, z, C4);
    q = pfma(q, z, C3);
    q = pfma(q, z, C2);
    q = pfma(q, z, C1);
    ull r  = pfma(pmul(q, z), s, s);             // asin(s)
    ull res = pfma(r, NEG2, PIHALF);             // pi/2 - 2r
    float ra, rb; UNPK(ra, rb, res);
    return pk2(copysignf(ra, xa), copysignf(rb, xb));
}

__global__ void __launch_bounds__(256, 5)
writhe_kernel(const float* __restrict__ xyz,
              const int4* __restrict__ segs,
              float* __restrict__ out,
              int n_seg, int frames_per_chunk) {
    int s = blockIdx.x * blockDim.x + threadIdx.x;
    if (s >= n_seg) return;

    const int4 sg = segs[s];
    const int f0 = blockIdx.y * frames_per_chunk;
    const float* fb = xyz + (size_t)f0 * FRAME_STRIDE;

    // per-atom pointers; frame B accessed at constant +FRAME_STRIDE imm offset
    const float* q1 = fb + sg.x * 3;
    const float* q2 = fb + sg.y * 3;
    const float* q3 = fb + sg.z * 3;
    const float* q4 = fb + sg.w * 3;

    float* op = out + (size_t)f0 * n_seg + s;

    const ull NEG1 = pk2(-1.0f, -1.0f);
    const float INV2PI = 0.15915494309189535f;

    const int npairs = frames_per_chunk >> 1;
    const bool odd = (frames_per_chunk & 1) != 0;

    for (int p = 0; p < npairs + (odd ? 1 : 0); ++p) {
        // For the odd trailing frame, lane B duplicates lane A (result discarded)
        const int fB = (p < npairs) ? FRAME_STRIDE : 0;

        ull P1x = pk2(__ldg(q1),     __ldg(q1 + fB));
        ull P1y = pk2(__ldg(q1 + 1), __ldg(q1 + fB + 1));
        ull P1z = pk2(__ldg(q1 + 2), __ldg(q1 + fB + 2));
        ull P2x = pk2(__ldg(q2),     __ldg(q2 + fB));
        ull P2y = pk2(__ldg(q2 + 1), __ldg(q2 + fB + 1));
        ull P2z = pk2(__ldg(q2 + 2), __ldg(q2 + fB + 2));
        ull P3x = pk2(__ldg(q3),     __ldg(q3 + fB));
        ull P3y = pk2(__ldg(q3 + 1), __ldg(q3 + fB + 1));
        ull P3z = pk2(__ldg(q3 + 2), __ldg(q3 + fB + 2));
        ull P4x = pk2(__ldg(q4),     __ldg(q4 + fB));
        ull P4y = pk2(__ldg(q4 + 1), __ldg(q4 + fB + 1));
        ull P4z = pk2(__ldg(q4 + 2), __ldg(q4 + fB + 2));

        q1 += 2 * FRAME_STRIDE; q2 += 2 * FRAME_STRIDE;
        q3 += 2 * FRAME_STRIDE; q4 += 2 * FRAME_STRIDE;

        ull r12x = psub(P2x, P1x, NEG1), r12y = psub(P2y, P1y, NEG1), r12z = psub(P2z, P1z, NEG1);
        ull r13x = psub(P3x, P1x, NEG1), r13y = psub(P3y, P1y, NEG1), r13z = psub(P3z, P1z, NEG1);
        ull r14x = psub(P4x, P1x, NEG1), r14y = psub(P4y, P1y, NEG1), r14z = psub(P4z, P1z, NEG1);

        ull n12x = pneg(r12x, NEG1), n12y = pneg(r12y, NEG1), n12z = pneg(r12z, NEG1);
        ull n13x = pneg(r13x, NEG1), n13y = pneg(r13y, NEG1), n13z = pneg(r13z, NEG1);

        // c1 = r13 x r14 ; c2 = r12 x r14 ; c4m = r12 x r13 (= -c4) ; c3 = c2 - c4m - c1
        ull c1x = pfma(n13z, r14y, pmul(r13y, r14z));
        ull c1y = pfma(n13x, r14z, pmul(r13z, r14x));
        ull c1z = pfma(n13y, r14x, pmul(r13x, r14y));
        ull c2x = pfma(n12z, r14y, pmul(r12y, r14z));
        ull c2y = pfma(n12x, r14z, pmul(r12z, r14x));
        ull c2z = pfma(n12y, r14x, pmul(r12x, r14y));
        ull c4x = pfma(n12z, r13y, pmul(r12y, r13z));
        ull c4y = pfma(n12x, r13z, pmul(r12z, r13x));
        ull c4z = pfma(n12y, r13x, pmul(r12x, r13y));
        ull c3x = psub(psub(c2x, c4x, NEG1), c1x, NEG1);
        ull c3y = psub(psub(c2y, c4y, NEG1), c1y, NEG1);
        ull c3z = psub(psub(c2z, c4z, NEG1), c1z, NEG1);

        ull g1 = pdot(c1x, c1y, c1z, c1x, c1y, c1z);
        ull g2 = pdot(c2x, c2y, c2z, c2x, c2y, c2z);
        ull g3 = pdot(c3x, c3y, c3z, c3x, c3y, c3z);
        ull g4 = pdot(c4x, c4y, c4z, c4x, c4y, c4z);

        ull h12 = pdot(c1x, c1y, c1z, c2x, c2y, c2z);
        ull h23 = pdot(c2x, c2y, c2z, c3x, c3y, c3z);
        ull h34 = pdot(c3x, c3y, c3z, c4x, c4y, c4z);
        ull h41 = pdot(c4x, c4y, c4z, c1x, c1y, c1z);

        ull psv = pdot(c2x, c2y, c2z, r13x, r13y, r13z);   // sv = -this

        float g1a, g1b, g2a, g2b, g3a, g3b, g4a, g4b;
        UNPK(g1a, g1b, g1); UNPK(g2a, g2b, g2);
        UNPK(g3a, g3b, g3); UNPK(g4a, g4b, g4);
        ull I1 = pk2(rsqrtf(g1a), rsqrtf(g1b));
        ull I2 = pk2(rsqrtf(g2a), rsqrtf(g2b));
        ull I3 = pk2(rsqrtf(g3a), rsqrtf(g3b));
        ull I4 = pk2(rsqrtf(g4a), rsqrtf(g4b));

        ull d12 = pmul(pmul(h12, I1), I2);
        ull d23 = pmul(pmul(h23, I2), I3);
        ull d34 = pmul(pmul(h34, I3), I4);   // = -dot(n3,n4)
        ull d41 = pmul(pmul(h41, I4), I1);   // = -dot(n4,n1)

        // theta = asin(d12) + asin(d23) - asin(d34) - asin(d41)
        ull theta = psub(psub(padd(pasin_u(d12), pasin_u(d23)), pasin_u(d34), NEG1),
                         pasin_u(d41), NEG1);

        float ta, tb, sva, svb;
        UNPK(ta, tb, theta);
        UNPK(sva, svb, psv);

        // sign(-sv) folded with 1/(2*pi)
        float ka = (sva < 0.0f) ? INV2PI : ((sva > 0.0f) ? -INV2PI : 0.0f);
        float kb = (svb < 0.0f) ? INV2PI : ((svb > 0.0f) ? -INV2PI : 0.0f);

        op[0] = ta * ka;
        if (p < npairs) op[n_seg] = tb * kb;
        op += 2 * (size_t)n_seg;
    }
}

extern "C" void kernel_launch(void* const* d_in, const int* in_sizes, int n_in,
                              void* d_out, int out_size) {
    const float* xyz = (const float*)d_in[0];
    const int4* segs = (const int4*)d_in[1];
    float* out = (float*)d_out;

    int n_seg = in_sizes[1] / 4;
    int n_frames = in_sizes[0] / FRAME_STRIDE;

    int chunks = FRAME_CHUNKS;
    if (n_frames % chunks != 0) chunks = 1;
    int frames_per_chunk = n_frames / chunks;

    int threads = 256;
    dim3 grid((n_seg + threads - 1) / threads, chunks);
    writhe_kernel<<<grid, threads>>>(xyz, segs, out, n_seg, frames_per_chunk);
}

// round 5
// speedup vs baseline: 1.8860x; 1.1949x over previous
#include <cuda_runtime.h>
#include <cuda_bf16.h>

#define N_ATOMS 512
#define FRAME_STRIDE (N_ATOMS * 3)
#define NROWS 509            // i in [0, 508]; row i has L_i = 509 - i segments
#define RUN 4                // consecutive j per thread
#define R_TOTAL 32640        // sum_i ceil(L_i / RUN)
#define NSEG_EXPECT 129795

typedef unsigned long long ull;

// ---------- packed f32x2 primitives ----------
__device__ __forceinline__ ull pk2(float lo, float hi) {
    ull r;
    asm("mov.b64 %0, {%1, %2};" : "=l"(r) : "f"(lo), "f"(hi));
    return r;
}
#define UNPK(lo, hi, v) asm("mov.b64 {%0, %1}, %2;" : "=f"(lo), "=f"(hi) : "l"(v))

__device__ __forceinline__ ull pmul(ull a, ull b) {
    ull d; asm("mul.rn.f32x2 %0, %1, %2;" : "=l"(d) : "l"(a), "l"(b)); return d;
}
__device__ __forceinline__ ull padd(ull a, ull b) {
    ull d; asm("add.rn.f32x2 %0, %1, %2;" : "=l"(d) : "l"(a), "l"(b)); return d;
}
__device__ __forceinline__ ull pfma(ull a, ull b, ull c) {
    ull d; asm("fma.rn.f32x2 %0, %1, %2, %3;" : "=l"(d) : "l"(a), "l"(b), "l"(c)); return d;
}
__device__ __forceinline__ ull psub(ull a, ull b, ull neg1) { return pfma(b, neg1, a); }
__device__ __forceinline__ ull pneg(ull a, ull neg1) { return pmul(a, neg1); }
__device__ __forceinline__ ull pdot(ull ax, ull ay, ull az, ull bx, ull by, ull bz) {
    return pfma(ax, bx, pfma(ay, by, pmul(az, bz)));
}
__device__ __forceinline__ float sqrt_approx(float z) {
    float r; asm("sqrt.approx.f32 %0, %1;" : "=f"(r) : "f"(z)); return r;
}

// Uniform branch-free asin (clamped): asin(a) = pi/2 - 2*asin(sqrt((1-a)/2))
__device__ __forceinline__ ull pasin_u(ull x) {
    const ull NEGHALF = pk2(-0.5f, -0.5f);
    const ull HALF    = pk2(0.5f, 0.5f);
    const ull NEG2    = pk2(-2.0f, -2.0f);
    const ull PIHALF  = pk2(1.5707963705062866f, 1.5707963705062866f);
    const ull C5 = pk2(4.2163199048e-2f, 4.2163199048e-2f);
    const ull C4 = pk2(2.4181311049e-2f, 2.4181311049e-2f);
    const ull C3 = pk2(4.5470025998e-2f, 4.5470025998e-2f);
    const ull C2 = pk2(7.4953002686e-2f, 7.4953002686e-2f);
    const ull C1 = pk2(1.6666752422e-1f, 1.6666752422e-1f);

    float xa, xb; UNPK(xa, xb, x);
    float aa = fminf(fabsf(xa), 1.0f);
    float ab = fminf(fabsf(xb), 1.0f);
    ull ap = pk2(aa, ab);
    ull z  = pfma(ap, NEGHALF, HALF);
    float za, zb; UNPK(za, zb, z);
    ull s  = pk2(sqrt_approx(za), sqrt_approx(zb));
    ull q  = pfma(C5, z, C4);
    q = pfma(q, z, C3);
    q = pfma(q, z, C2);
    q = pfma(q, z, C1);
    ull r  = pfma(pmul(q, z), s, s);
    ull res = pfma(r, NEG2, PIHALF);
    float ra, rb; UNPK(ra, rb, res);
    return pk2(copysignf(ra, xa), copysignf(rb, xb));
}

// prefix of per-row run counts, rows counted from the short end:
// S(n) = sum_{L=1}^{n} ceil(L/4) = (q+1)*(2q+r) with n = 4q+r
__device__ __forceinline__ int S4(int n) {
    int q = n >> 2, r = n & 3;
    return (q + 1) * (2 * q + r);
}

__global__ void writhe_rows_kernel(const float* __restrict__ xyz,
                                   float* __restrict__ out,
                                   int n_seg, int frames_per_chunk) {
    int t = blockIdx.x * blockDim.x + threadIdx.x;
    if (t >= R_TOTAL) return;

    // invert run index -> (row i, chunk)
    int u = R_TOTAL - t;                    // in [1, R_TOTAL]
    int lo = 1, hi = NROWS;
    while (lo < hi) {                       // smallest n with S4(n) >= u
        int mid = (lo + hi) >> 1;
        if (S4(mid) >= u) hi = mid; else lo = mid + 1;
    }
    const int n = lo;
    const int i = NROWS - n;
    const int chunk = S4(n) - u;
    const int L = NROWS - i;
    const int count = min(RUN, L - RUN * chunk);
    const int j0 = i + 2 + RUN * chunk;
    const int out_base = (i * (2 * NROWS + 1 - i)) / 2 + RUN * chunk;

    // float-offsets of atoms j0..j0+4 (clamped; clamped ones are store-masked)
    const int oj0 = 3 * j0;
    int ojs[RUN];
    ojs[0] = 3 * min(j0 + 1, N_ATOMS - 1);
    ojs[1] = 3 * min(j0 + 2, N_ATOMS - 1);
    ojs[2] = 3 * min(j0 + 3, N_ATOMS - 1);
    ojs[3] = 3 * min(j0 + 4, N_ATOMS - 1);

    const int f0 = blockIdx.y * frames_per_chunk;
    const float* qi = xyz + (size_t)f0 * FRAME_STRIDE + 3 * i;   // atoms i, i+1
    const float* qj = xyz + (size_t)f0 * FRAME_STRIDE;           // + ojs
    float* op = out + (size_t)f0 * n_seg + out_base;

    const ull NEG1 = pk2(-1.0f, -1.0f);
    const float INV2PI = 0.15915494309189535f;

    const int npairs = frames_per_chunk >> 1;
    const bool odd = (frames_per_chunk & 1) != 0;

    for (int p = 0; p < npairs + (odd ? 1 : 0); ++p) {
        const int fB = (p < npairs) ? FRAME_STRIDE : 0;   // odd tail: dup lane A
#define LD2(q, o) pk2(__ldg((q) + (o)), __ldg((q) + (o) + fB))

        ull P1x = LD2(qi, 0), P1y = LD2(qi, 1), P1z = LD2(qi, 2);
        ull P2x = LD2(qi, 3), P2y = LD2(qi, 4), P2z = LD2(qi, 5);

        ull r12x = psub(P2x, P1x, NEG1), r12y = psub(P2y, P1y, NEG1), r12z = psub(P2z, P1z, NEG1);
        ull n12x = pneg(r12x, NEG1),     n12y = pneg(r12y, NEG1),     n12z = pneg(r12z, NEG1);

        ull Qx = LD2(qj, oj0), Qy = LD2(qj, oj0 + 1), Qz = LD2(qj, oj0 + 2);
        ull r13x = psub(Qx, P1x, NEG1), r13y = psub(Qy, P1y, NEG1), r13z = psub(Qz, P1z, NEG1);
        ull n13x = pneg(r13x, NEG1),    n13y = pneg(r13y, NEG1),    n13z = pneg(r13z, NEG1);

        // c4m(j0) = r12 x r13
        ull c4x = pfma(n12z, r13y, pmul(r12y, r13z));
        ull c4y = pfma(n12x, r13z, pmul(r12z, r13x));
        ull c4z = pfma(n12y, r13x, pmul(r12x, r13y));
        ull g4 = pdot(c4x, c4y, c4z, c4x, c4y, c4z);
        float g4a, g4b; UNPK(g4a, g4b, g4);
        ull I4 = pk2(rsqrtf(g4a), rsqrtf(g4b));

        #pragma unroll
        for (int k = 0; k < RUN; ++k) {
            const int oo = ojs[k];
            ull Nx = LD2(qj, oo), Ny = LD2(qj, oo + 1), Nz = LD2(qj, oo + 2);
            ull r14x = psub(Nx, P1x, NEG1), r14y = psub(Ny, P1y, NEG1), r14z = psub(Nz, P1z, NEG1);
            ull n14x = pneg(r14x, NEG1),    n14y = pneg(r14y, NEG1),    n14z = pneg(r14z, NEG1);

            // c1 = r13 x r14 ; c2 = r12 x r14 ; c3 = c2 - c4m - c1
            ull c1x = pfma(n13z, r14y, pmul(r13y, r14z));
            ull c1y = pfma(n13x, r14z, pmul(r13z, r14x));
            ull c1z = pfma(n13y, r14x, pmul(r13x, r14y));
            ull c2x = pfma(n12z, r14y, pmul(r12y, r14z));
            ull c2y = pfma(n12x, r14z, pmul(r12z, r14x));
            ull c2z = pfma(n12y, r14x, pmul(r12x, r14y));
            ull c3x = psub(psub(c2x, c4x, NEG1), c1x, NEG1);
            ull c3y = psub(psub(c2y, c4y, NEG1), c1y, NEG1);
            ull c3z = psub(psub(c2z, c4z, NEG1), c1z, NEG1);

            ull g1 = pdot(c1x, c1y, c1z, c1x, c1y, c1z);
            ull g2 = pdot(c2x, c2y, c2z, c2x, c2y, c2z);
            ull g3 = pdot(c3x, c3y, c3z, c3x, c3y, c3z);

            ull h12 = pdot(c1x, c1y, c1z, c2x, c2y, c2z);
            ull h23 = pdot(c2x, c2y, c2z, c3x, c3y, c3z);
            ull h34 = pdot(c3x, c3y, c3z, c4x, c4y, c4z);   // dot(c3, c4m) = -dot(c3,c4)
            ull h41 = pdot(c4x, c4y, c4z, c1x, c1y, c1z);   // dot(c4m,c1) = -dot(c4,c1)
            ull psv = pdot(c2x, c2y, c2z, r13x, r13y, r13z); // sv = -this

            float g1a, g1b, g2a, g2b, g3a, g3b;
            UNPK(g1a, g1b, g1); UNPK(g2a, g2b, g2); UNPK(g3a, g3b, g3);
            ull I1 = pk2(rsqrtf(g1a), rsqrtf(g1b));
            ull I2 = pk2(rsqrtf(g2a), rsqrtf(g2b));
            ull I3 = pk2(rsqrtf(g3a), rsqrtf(g3b));

            ull d12 = pmul(pmul(h12, I1), I2);
            ull d23 = pmul(pmul(h23, I2), I3);
            ull d34 = pmul(pmul(h34, I3), I4);
            ull d41 = pmul(pmul(h41, I4), I1);

            // theta = asin(d12)+asin(d23)-asin(d34)-asin(d41)
            ull theta = psub(psub(padd(pasin_u(d12), pasin_u(d23)), pasin_u(d34), NEG1),
                             pasin_u(d41), NEG1);

            float ta, tb, sva, svb;
            UNPK(ta, tb, theta);
            UNPK(sva, svb, psv);
            float ka = (sva < 0.0f) ? INV2PI : ((sva > 0.0f) ? -INV2PI : 0.0f);
            float kb = (svb < 0.0f) ? INV2PI : ((svb > 0.0f) ? -INV2PI : 0.0f);

            if (k < count) {
                op[k] = ta * ka;
                if (fB) op[k + n_seg] = tb * kb;
            }

            // carry to next j: r13 <- r14, n13 <- n14, c4m <- c2, I4 <- I2
            r13x = r14x; r13y = r14y; r13z = r14z;
            n13x = n14x; n13y = n14y; n13z = n14z;
            c4x = c2x; c4y = c2y; c4z = c2z;
            I4 = I2;
        }
#undef LD2
        qi += 2 * FRAME_STRIDE;
        qj += 2 * FRAME_STRIDE;
        op += 2 * (size_t)n_seg;
    }
}

// ---------- generic fallback (shape mismatch insurance) ----------
struct f3 { float x, y, z; };
__device__ __forceinline__ f3 fsub3(f3 a, f3 b) { return {a.x-b.x, a.y-b.y, a.z-b.z}; }
__device__ __forceinline__ f3 fcross3(f3 a, f3 b) {
    return { fmaf(a.y,b.z,-a.z*b.y), fmaf(a.z,b.x,-a.x*b.z), fmaf(a.x,b.y,-a.y*b.x) };
}
__device__ __forceinline__ float fdot3(f3 a, f3 b) { return fmaf(a.x,b.x,fmaf(a.y,b.y,a.z*b.z)); }
__device__ __forceinline__ f3 fld3(const float* p) { return { __ldg(p), __ldg(p+1), __ldg(p+2) }; }
__device__ __forceinline__ float fasin(float x) { return asinf(fminf(fmaxf(x,-1.0f),1.0f)); }

__global__ void writhe_generic_kernel(const float* __restrict__ xyz,
                                      const int4* __restrict__ segs,
                                      float* __restrict__ out,
                                      int n_seg, int n_frames) {
    int s = blockIdx.x * blockDim.x + threadIdx.x;
    if (s >= n_seg) return;
    int4 sg = segs[s];
    for (int f = 0; f < n_frames; ++f) {
        const float* b = xyz + (size_t)f * FRAME_STRIDE;
        f3 p1 = fld3(b + sg.x*3), p2 = fld3(b + sg.y*3);
        f3 p3 = fld3(b + sg.z*3), p4 = fld3(b + sg.w*3);
        f3 r12 = fsub3(p2,p1), r13 = fsub3(p3,p1), r14 = fsub3(p4,p1);
        f3 r23 = fsub3(p3,p2), r24 = fsub3(p4,p2), r34 = fsub3(p4,p3);
        f3 c1 = fcross3(r13,r14), c2 = fcross3(r14,r24), c3 = fcross3(r24,r23), c4 = fcross3(r23,r13);
        float i1 = rsqrtf(fdot3(c1,c1)), i2 = rsqrtf(fdot3(c2,c2));
        float i3 = rsqrtf(fdot3(c3,c3)), i4 = rsqrtf(fdot3(c4,c4));
        float th = fasin(fdot3(c1,c2)*i1*i2) + fasin(fdot3(c2,c3)*i2*i3)
                 + fasin(fdot3(c3,c4)*i3*i4) + fasin(fdot3(c4,c1)*i4*i1);
        float sv = fdot3(fcross3(r34,r12), r13);
        float sign = (sv > 0.f) ? 1.f : ((sv < 0.f) ? -1.f : 0.f);
        out[(size_t)f * n_seg + s] = th * sign * 0.15915494309189535f;
    }
}

extern "C" void kernel_launch(void* const* d_in, const int* in_sizes, int n_in,
                              void* d_out, int out_size) {
    const float* xyz = (const float*)d_in[0];
    const int4* segs = (const int4*)d_in[1];
    float* out = (float*)d_out;

    int n_seg = in_sizes[1] / 4;
    int n_frames = in_sizes[0] / FRAME_STRIDE;

    if (n_seg == NSEG_EXPECT) {
        int chunks = 1;
        if (n_frames % 16 == 0) chunks = 16;
        else if (n_frames % 8 == 0) chunks = 8;
        else if (n_frames % 4 == 0) chunks = 4;
        int fpc = n_frames / chunks;
        int threads = 128;
        dim3 grid((R_TOTAL + threads - 1) / threads, chunks);
        writhe_rows_kernel<<<grid, threads>>>(xyz, out, n_seg, fpc);
    } else {
        int threads = 256;
        writhe_generic_kernel<<<(n_seg + threads - 1) / threads, threads>>>(
            xyz, segs, out, n_seg, n_frames);
    }
}